// round 16
// baseline (speedup 1.0000x reference)
#include <cuda_runtime.h>
#include <cuda_fp16.h>
#include <cstdint>
#include <cstddef>

// Correlation as band-Gram fp16 mma.sync GEMM (m16n8k16, fp32 accumulate).
// Pass 1: reformat d2 -> g_B, per (b,row): [par][t:7][kp2:3][lane:32][e:4],
//   one uint4 STG per (blk,lane).
// Pass 2: block = (y-pair, b), 384 thr, 2 blocks/SM. Rows y0, y0+2 share B
//   rows; 23 uniform steps, one barrier each. B via cp.async double buffer
//   (WAR-safe order). Stage in output coords [j][x]; writeout = raw copy with
//   ALL index math hoisted out of the loop. sc folded into A pack. Tile count
//   templated.

#define NT   384
#define XROW 100                           // stage row stride (floats)
#define STAGE_H (21 * XROW)                // 2100 floats per y-half
#define STAGE_FLOATS (2 * STAGE_H)         // 4200 per buffer
#define B_U32   5376                       // u32 words per row (2 par x 2688)
#define B_BYTES 21504
#define STAGE_OFF_B (2 * B_BYTES)          // 43008
#define SMEM_BYTES (STAGE_OFF_B + 2 * STAGE_FLOATS * 4)   // 76608 -> 2 blk/SM

#define GB_N 2752512                       // 8*64*5376
__device__ uint32_t g_B[GB_N];

__device__ __forceinline__ uint32_t packh2(float a, float b) {
    __half2 h = __floats2half2_rn(a, b);
    return *(uint32_t*)&h;
}
__device__ __forceinline__ uint32_t s2u(const void* p) {
    uint32_t a;
    asm("{ .reg .u64 t; cvta.to.shared.u64 t, %1; cvt.u32.u64 %0, t; }"
        : "=r"(a) : "l"(p));
    return a;
}
__device__ __forceinline__ void mma16(float* c, const uint32_t* a,
                                      uint32_t b0, uint32_t b1) {
    asm volatile(
        "mma.sync.aligned.m16n8k16.row.col.f32.f16.f16.f32 "
        "{%0,%1,%2,%3}, {%4,%5,%6,%7}, {%8,%9}, {%0,%1,%2,%3};"
        : "+f"(c[0]), "+f"(c[1]), "+f"(c[2]), "+f"(c[3])
        : "r"(a[0]), "r"(a[1]), "r"(a[2]), "r"(a[3]), "r"(b0), "r"(b1));
}

// ---------------- pass 1: reformat d2 -> g_B (smem transpose) --------------
__global__ void __launch_bounds__(256) reformat(const float* __restrict__ d2) {
    __shared__ float t[96 * 100];
    const int td  = threadIdx.x;
    const int row = blockIdx.x & 63;
    const int b   = blockIdx.x >> 6;

    const float* src = d2 + ((size_t)b * 96 * 64 + row) * 96;
    #pragma unroll
    for (int it = 0; it < 9; ++it) {
        int lin = it * 256 + td;
        int c = lin / 24, xq = lin - c * 24;
        float4 v = *(const float4*)(src + (size_t)c * 6144 + 4 * xq);
        *(float4*)(t + c * 100 + 4 * xq) = v;
    }
    __syncthreads();

    uint32_t* dst = g_B + (size_t)(b * 64 + row) * B_U32;
    #pragma unroll
    for (int it = 0; it < 6; ++it) {       // 1344 uint4 = 5376 words
        int lin = it * 256 + td;
        if (lin < 1344) {
            int l = lin & 31;
            int blk = lin >> 5;            // ((par*7 + tt)*3 + kp2)
            int kp2 = blk % 3, pt = blk / 3;
            int tt = pt % 7, par = pt / 7;
            int g = l >> 2, q = l & 3;
            int x = 16 * tt + 2 * g - 4 + par;
            uint4 wv;
            if ((unsigned)x < 96u) {
                const float* col = t + x;
                uint32_t* wp = &wv.x;
                #pragma unroll
                for (int e = 0; e < 4; ++e) {
                    int kp = 2 * kp2 + (e >> 1);
                    int c = 16 * kp + 2 * q + 8 * (e & 1);
                    wp[e] = packh2(col[c * 100], col[(c + 1) * 100]);
                }
            } else {
                wv.x = wv.y = wv.z = wv.w = 0u;
            }
            *(uint4*)(dst + 4 * lin) = wv;
        }
    }
}

// ---------------- pass 2 helpers ----------------
template <int NTT>
__device__ __forceinline__ void compute_tiles(
    float (*acc)[4], const uint32_t (*A)[4], const uint32_t* bb,
    float* stg, int t0, int m, int g, int q, int xbase)
{
    #pragma unroll
    for (int kp2 = 0; kp2 < 3; ++kp2) {
        #pragma unroll
        for (int tt = 0; tt < NTT; ++tt) {
            uint4 v = *(const uint4*)(bb + tt * 384 + kp2 * 128);
            mma16(acc[tt], A[2 * kp2],     v.x, v.y);
            mma16(acc[tt], A[2 * kp2 + 1], v.z, v.w);
        }
    }
    // stage accs in output coords: stage[j][x]
    #pragma unroll
    for (int tt = 0; tt < NTT; ++tt) {
        int j0 = 8 * (t0 + tt + 1) + 2 * q - 16 * m - g;
        int j1 = j0 - 8;
        if ((unsigned)j0 < 21u)       stg[j0 * XROW + xbase]            = acc[tt][0];
        if ((unsigned)(j0 + 1) < 21u) stg[(j0 + 1) * XROW + xbase]      = acc[tt][1];
        if ((unsigned)j1 < 21u)       stg[j1 * XROW + xbase + 16]       = acc[tt][2];
        if ((unsigned)(j1 + 1) < 21u) stg[(j1 + 1) * XROW + xbase + 16] = acc[tt][3];
        acc[tt][0] = acc[tt][1] = acc[tt][2] = acc[tt][3] = 0.f;
    }
}

// ---------------- pass 2: paired-y GEMM ----------------
__global__ void __launch_bounds__(NT, 2) corr_mma(
    const float* __restrict__ d1,
    const float* __restrict__ s1, const float* __restrict__ s2,
    const float* __restrict__ osc, float* __restrict__ out)
{
    extern __shared__ char smc[];
    uint32_t* bsm = (uint32_t*)smc;                  // [2][B_U32]
    float* stage = (float*)(smc + STAGE_OFF_B);      // [2 buf][2h][21 j][XROW]
    const uint32_t bsm_u = s2u(smc);

    const int td = threadIdx.x;
    const int w = td >> 5, l = td & 31;
    const int h = w / 6, w6 = w % 6, m = w6 >> 1, par = w6 & 1;
    const int g = l >> 2, q = l & 3;
    const int t0 = (m == 0) ? 0 : ((m == 1) ? 1 : 3);

    const int yp = blockIdx.x;
    const int y0 = 4 * (yp >> 1) + (yp & 1);
    const int b = blockIdx.y;
    const int y = y0 + 2 * h;

    // zero both stage buffers (unwritten (j,x) slots = OOB x' -> must read 0)
    {
        float4 zv = make_float4(0.f, 0.f, 0.f, 0.f);
        float4* p = (float4*)stage;
        for (int i = td; i < 2 * STAGE_FLOATS / 4; i += NT) p[i] = zv;
    }

    // ---- per-thread writeout constants (hoisted: 384 = 16*24) ----
    const int xqw = td % 24;
    const int jA  = td / 24;                 // 0..15 ; jB = jA+16
    const bool hasB = td < 120;              // jB in 16..20
    const int soffA = jA * XROW + 4 * xqw;
    const int soffB = soffA + 16 * XROW;
    float* wbase = out + (size_t)b * 441 * 6144 + y0 * 96
                   + jA * 6144 + 4 * xqw;

    // A frags (fp16, register-resident, sc folded in)
    const float scv = s1[0] * s2[0] / (96.0f * osc[0]);
    uint32_t A[6][4];
    {
        int xg = 2 * (16 * m + g) + par;
        int xg8 = xg + 16;
        const float* p0 = d1 + ((size_t)(b * 96) * 64 + y) * 96;
        #pragma unroll
        for (int kp = 0; kp < 6; ++kp) {
            const float* pc = p0 + (size_t)(16 * kp + 2 * q) * 6144;
            A[kp][0] = packh2(pc[xg] * scv,             pc[6144 + xg] * scv);
            A[kp][1] = packh2(pc[xg8] * scv,            pc[6144 + xg8] * scv);
            A[kp][2] = packh2(pc[8 * 6144 + xg] * scv,  pc[9 * 6144 + xg] * scv);
            A[kp][3] = packh2(pc[8 * 6144 + xg8] * scv, pc[9 * 6144 + xg8] * scv);
        }
    }

    float acc[5][4];
    #pragma unroll
    for (int tt = 0; tt < 5; ++tt)
        #pragma unroll
        for (int e = 0; e < 4; ++e) acc[tt][e] = 0.f;

    const size_t gbase = (size_t)(b * 64) * B_U32;
    const int xbase = 32 * m + 2 * g + par;

    auto prefetch = [&](int s_idx, int bi) {
        int row = y0 - 20 + 2 * s_idx;
        if (s_idx <= 21 && (unsigned)row < 64u) {
            const char* gp = (const char*)(g_B + gbase + (size_t)row * B_U32);
            uint32_t sa = bsm_u + bi * B_BYTES;
            #pragma unroll
            for (int u = 0; u < 4; ++u) {
                int idx = u * NT + td;
                if (idx < 1344)
                    asm volatile("cp.async.cg.shared.global [%0], [%1], 16;"
                                 :: "r"(sa + idx * 16), "l"(gp + idx * 16)
                                 : "memory");
            }
        }
        asm volatile("cp.async.commit_group;" ::: "memory");
    };

    prefetch(0, 0);

    for (int s = 0; s < 23; ++s) {
        asm volatile("cp.async.wait_group 0;" ::: "memory");
        __syncthreads();

        // P(s+1) into buffer (s+1)&1: last read in compute(s-1), retired above.
        prefetch(s + 1, (s + 1) & 1);

        // ---- writeout of staged step s-1 (other stage buffer) ----
        if (s >= 1) {
            const float* stb = stage + ((s - 1) & 1) * STAGE_FLOATS;
            const bool vp = (unsigned)(y0 + 2 * (s - 1) - 20) < 64u;
            const float4 z4 = make_float4(0.f, 0.f, 0.f, 0.f);
            if (s <= 21) {                               // half 0: y0, iv = s-1
                size_t off = (size_t)(s - 1) * 129024;
                float4 v = vp ? *(const float4*)(stb + soffA) : z4;
                __stcs((float4*)(wbase + off), v);
                if (hasB) {
                    float4 v2 = vp ? *(const float4*)(stb + soffB) : z4;
                    __stcs((float4*)(wbase + off + 98304), v2);
                }
            }
            if (s >= 2) {                                // half 1: y0+2, iv = s-2
                size_t off = (size_t)(s - 2) * 129024;
                const float* st1 = stb + STAGE_H;
                float4 v = vp ? *(const float4*)(st1 + soffA) : z4;
                __stcs((float4*)(wbase + 192 + off), v);
                if (hasB) {
                    float4 v2 = vp ? *(const float4*)(st1 + soffB) : z4;
                    __stcs((float4*)(wbase + 192 + off + 98304), v2);
                }
            }
        }

        // ---- compute(s) into stage buffer s&1 ----
        const int r = y0 + 2 * s - 20;
        const bool vr = (unsigned)r < 64u;
        const int i = s - h;
        if (s <= 21 && vr && (unsigned)i < 21u) {
            const uint32_t* bb = bsm + (s & 1) * B_U32 + par * 2688
                                 + t0 * 384 + 4 * l;
            float* stg = stage + (s & 1) * STAGE_FLOATS + h * STAGE_H;
            if (m == 1) compute_tiles<5>(acc, A, bb, stg, t0, m, g, q, xbase);
            else        compute_tiles<4>(acc, A, bb, stg, t0, m, g, q, xbase);
        }
    }
}

extern "C" void kernel_launch(void* const* d_in, const int* in_sizes, int n_in,
                              void* d_out, int out_size) {
    const float* data1     = (const float*)d_in[0];
    const float* data2     = (const float*)d_in[1];
    const float* scale1    = (const float*)d_in[2];
    const float* scale2    = (const float*)d_in[3];
    /* d_in[4] = inter_scale, unused by the reference math */
    const float* out_scale = (const float*)d_in[5];

    reformat<<<512, 256>>>(data2);

    cudaFuncSetAttribute(corr_mma, cudaFuncAttributeMaxDynamicSharedMemorySize,
                         SMEM_BYTES);
    dim3 grid(32, 8);   // (y-pair, b)
    corr_mma<<<grid, NT, SMEM_BYTES>>>(data1, scale1, scale2, out_scale,
                                       (float*)d_out);
}

// round 17
// speedup vs baseline: 1.0006x; 1.0006x over previous
#include <cuda_runtime.h>
#include <cuda_fp16.h>
#include <cstdint>
#include <cstddef>

// Correlation as band-Gram fp16 mma.sync GEMM (m16n8k16, fp32 accumulate).
// Pass 1: reformat d2 -> g_B, per (b,row): [par][t:7][kp2:3][lane:32][e:4],
//   one uint4 STG per (blk,lane).
// Pass 2: block = (y-pair, b), 384 thr, 2 blocks/SM. Rows y0, y0+2 share B
//   rows; 23 uniform steps, one barrier each. B via cp.async double buffer
//   (WAR-safe order). Stage in output coords [j][x]. WRITEOUT ONLY ON m0/m2
//   WARPS (m1 warps carry the 5th mma tile) -> balanced barrier arrival.

#define NT   384
#define XROW 100                           // stage row stride (floats)
#define STAGE_H (21 * XROW)                // 2100 floats per y-half
#define STAGE_FLOATS (2 * STAGE_H)         // 4200 per buffer
#define B_U32   5376                       // u32 words per row (2 par x 2688)
#define B_BYTES 21504
#define STAGE_OFF_B (2 * B_BYTES)          // 43008
#define SMEM_BYTES (STAGE_OFF_B + 2 * STAGE_FLOATS * 4)   // 76608 -> 2 blk/SM

#define GB_N 2752512                       // 8*64*5376
__device__ uint32_t g_B[GB_N];

__device__ __forceinline__ uint32_t packh2(float a, float b) {
    __half2 h = __floats2half2_rn(a, b);
    return *(uint32_t*)&h;
}
__device__ __forceinline__ uint32_t s2u(const void* p) {
    uint32_t a;
    asm("{ .reg .u64 t; cvta.to.shared.u64 t, %1; cvt.u32.u64 %0, t; }"
        : "=r"(a) : "l"(p));
    return a;
}
__device__ __forceinline__ void mma16(float* c, const uint32_t* a,
                                      uint32_t b0, uint32_t b1) {
    asm volatile(
        "mma.sync.aligned.m16n8k16.row.col.f32.f16.f16.f32 "
        "{%0,%1,%2,%3}, {%4,%5,%6,%7}, {%8,%9}, {%0,%1,%2,%3};"
        : "+f"(c[0]), "+f"(c[1]), "+f"(c[2]), "+f"(c[3])
        : "r"(a[0]), "r"(a[1]), "r"(a[2]), "r"(a[3]), "r"(b0), "r"(b1));
}

// ---------------- pass 1: reformat d2 -> g_B (smem transpose) --------------
__global__ void __launch_bounds__(256) reformat(const float* __restrict__ d2) {
    __shared__ float t[96 * 100];
    const int td  = threadIdx.x;
    const int row = blockIdx.x & 63;
    const int b   = blockIdx.x >> 6;

    const float* src = d2 + ((size_t)b * 96 * 64 + row) * 96;
    #pragma unroll
    for (int it = 0; it < 9; ++it) {
        int lin = it * 256 + td;
        int c = lin / 24, xq = lin - c * 24;
        float4 v = *(const float4*)(src + (size_t)c * 6144 + 4 * xq);
        *(float4*)(t + c * 100 + 4 * xq) = v;
    }
    __syncthreads();

    uint32_t* dst = g_B + (size_t)(b * 64 + row) * B_U32;
    #pragma unroll
    for (int it = 0; it < 6; ++it) {       // 1344 uint4 = 5376 words
        int lin = it * 256 + td;
        if (lin < 1344) {
            int l = lin & 31;
            int blk = lin >> 5;            // ((par*7 + tt)*3 + kp2)
            int kp2 = blk % 3, pt = blk / 3;
            int tt = pt % 7, par = pt / 7;
            int g = l >> 2, q = l & 3;
            int x = 16 * tt + 2 * g - 4 + par;
            uint4 wv;
            if ((unsigned)x < 96u) {
                const float* col = t + x;
                uint32_t* wp = &wv.x;
                #pragma unroll
                for (int e = 0; e < 4; ++e) {
                    int kp = 2 * kp2 + (e >> 1);
                    int c = 16 * kp + 2 * q + 8 * (e & 1);
                    wp[e] = packh2(col[c * 100], col[(c + 1) * 100]);
                }
            } else {
                wv.x = wv.y = wv.z = wv.w = 0u;
            }
            *(uint4*)(dst + 4 * lin) = wv;
        }
    }
}

// ---------------- pass 2 helpers ----------------
template <int NTT>
__device__ __forceinline__ void compute_tiles(
    float (*acc)[4], const uint32_t (*A)[4], const uint32_t* bb,
    float* stg, int t0, int m, int g, int q, int xbase)
{
    #pragma unroll
    for (int kp2 = 0; kp2 < 3; ++kp2) {
        #pragma unroll
        for (int tt = 0; tt < NTT; ++tt) {
            uint4 v = *(const uint4*)(bb + tt * 384 + kp2 * 128);
            mma16(acc[tt], A[2 * kp2],     v.x, v.y);
            mma16(acc[tt], A[2 * kp2 + 1], v.z, v.w);
        }
    }
    // stage accs in output coords: stage[j][x]
    #pragma unroll
    for (int tt = 0; tt < NTT; ++tt) {
        int j0 = 8 * (t0 + tt + 1) + 2 * q - 16 * m - g;
        int j1 = j0 - 8;
        if ((unsigned)j0 < 21u)       stg[j0 * XROW + xbase]            = acc[tt][0];
        if ((unsigned)(j0 + 1) < 21u) stg[(j0 + 1) * XROW + xbase]      = acc[tt][1];
        if ((unsigned)j1 < 21u)       stg[j1 * XROW + xbase + 16]       = acc[tt][2];
        if ((unsigned)(j1 + 1) < 21u) stg[(j1 + 1) * XROW + xbase + 16] = acc[tt][3];
        acc[tt][0] = acc[tt][1] = acc[tt][2] = acc[tt][3] = 0.f;
    }
}

// ---------------- pass 2: paired-y GEMM ----------------
__global__ void __launch_bounds__(NT, 2) corr_mma(
    const float* __restrict__ d1,
    const float* __restrict__ s1, const float* __restrict__ s2,
    const float* __restrict__ osc, float* __restrict__ out)
{
    extern __shared__ char smc[];
    uint32_t* bsm = (uint32_t*)smc;                  // [2][B_U32]
    float* stage = (float*)(smc + STAGE_OFF_B);      // [2 buf][2h][21 j][XROW]
    const uint32_t bsm_u = s2u(smc);

    const int td = threadIdx.x;
    const int w = td >> 5, l = td & 31;
    const int h = w / 6, w6 = w % 6, m = w6 >> 1, par = w6 & 1;
    const int g = l >> 2, q = l & 3;
    const int t0 = (m == 0) ? 0 : ((m == 1) ? 1 : 3);

    const int yp = blockIdx.x;
    const int y0 = 4 * (yp >> 1) + (yp & 1);
    const int b = blockIdx.y;
    const int y = y0 + 2 * h;

    // zero both stage buffers (unwritten (j,x) slots = OOB x' -> must read 0)
    {
        float4 zv = make_float4(0.f, 0.f, 0.f, 0.f);
        float4* p = (float4*)stage;
        for (int i = td; i < 2 * STAGE_FLOATS / 4; i += NT) p[i] = zv;
    }

    // ---- writeout role: m0/m2 warps only (m1 carries the 5th mma tile) ----
    const bool wo = (m != 1);
    int soff[4]; int cof[4]; unsigned whm = 0, okm = 0;
    {
        int kmap = (w6 == 0) ? 0 : (w6 == 1) ? 1 : (w6 == 4) ? 2 : 3;
        int wt = (h * 4 + kmap) * 32 + l;            // 0..255 among wo threads
        #pragma unroll
        for (int r2 = 0; r2 < 4; ++r2) {
            int slot = wt + 256 * r2;                // 0..1023, need < 1008
            int half = (slot >= 504);
            int rr = slot - 504 * half;
            int j = rr / 24, xq = rr - 24 * j;
            soff[r2] = half * STAGE_H + j * XROW + 4 * xq;
            cof[r2]  = j * 6144 + half * 192 - half * 129024 + 4 * xq;
            whm |= (unsigned)half << r2;
            okm |= (unsigned)(slot < 1008) << r2;
        }
    }
    float* outw = out + (size_t)b * 441 * 6144 + y0 * 96;

    // A frags (fp16, register-resident, sc folded in)
    const float scv = s1[0] * s2[0] / (96.0f * osc[0]);
    uint32_t A[6][4];
    {
        int xg = 2 * (16 * m + g) + par;
        int xg8 = xg + 16;
        const float* p0 = d1 + ((size_t)(b * 96) * 64 + y) * 96;
        #pragma unroll
        for (int kp = 0; kp < 6; ++kp) {
            const float* pc = p0 + (size_t)(16 * kp + 2 * q) * 6144;
            A[kp][0] = packh2(pc[xg] * scv,             pc[6144 + xg] * scv);
            A[kp][1] = packh2(pc[xg8] * scv,            pc[6144 + xg8] * scv);
            A[kp][2] = packh2(pc[8 * 6144 + xg] * scv,  pc[9 * 6144 + xg] * scv);
            A[kp][3] = packh2(pc[8 * 6144 + xg8] * scv, pc[9 * 6144 + xg8] * scv);
        }
    }

    float acc[5][4];
    #pragma unroll
    for (int tt = 0; tt < 5; ++tt)
        #pragma unroll
        for (int e = 0; e < 4; ++e) acc[tt][e] = 0.f;

    const size_t gbase = (size_t)(b * 64) * B_U32;
    const int xbase = 32 * m + 2 * g + par;

    auto prefetch = [&](int s_idx, int bi) {
        int row = y0 - 20 + 2 * s_idx;
        if (s_idx <= 21 && (unsigned)row < 64u) {
            const char* gp = (const char*)(g_B + gbase + (size_t)row * B_U32);
            uint32_t sa = bsm_u + bi * B_BYTES;
            #pragma unroll
            for (int u = 0; u < 4; ++u) {
                int idx = u * NT + td;
                if (idx < 1344)
                    asm volatile("cp.async.cg.shared.global [%0], [%1], 16;"
                                 :: "r"(sa + idx * 16), "l"(gp + idx * 16)
                                 : "memory");
            }
        }
        asm volatile("cp.async.commit_group;" ::: "memory");
    };

    prefetch(0, 0);

    for (int s = 0; s < 23; ++s) {
        asm volatile("cp.async.wait_group 0;" ::: "memory");
        __syncthreads();

        // P(s+1) into buffer (s+1)&1: last read in compute(s-1), retired above.
        prefetch(s + 1, (s + 1) & 1);

        // ---- writeout of staged step s-1 (m0/m2 warps only) ----
        if (wo && s >= 1) {
            const float* stb = stage + ((s - 1) & 1) * STAGE_FLOATS;
            const bool vp = (unsigned)(y0 + 2 * (s - 1) - 20) < 64u;
            float* pW = outw + (size_t)(s - 1) * 129024;
            const float4 z4 = make_float4(0.f, 0.f, 0.f, 0.f);
            #pragma unroll
            for (int r2 = 0; r2 < 4; ++r2) {
                if (okm & (1u << r2)) {
                    int iv = (s - 1) - (int)((whm >> r2) & 1u);
                    if ((unsigned)iv < 21u) {
                        float4 v = vp ? *(const float4*)(stb + soff[r2]) : z4;
                        __stcs((float4*)(pW + cof[r2]), v);
                    }
                }
            }
        }

        // ---- compute(s) into stage buffer s&1 ----
        const int r = y0 + 2 * s - 20;
        const bool vr = (unsigned)r < 64u;
        const int i = s - h;
        if (s <= 21 && vr && (unsigned)i < 21u) {
            const uint32_t* bb = bsm + (s & 1) * B_U32 + par * 2688
                                 + t0 * 384 + 4 * l;
            float* stg = stage + (s & 1) * STAGE_FLOATS + h * STAGE_H;
            if (m == 1) compute_tiles<5>(acc, A, bb, stg, t0, m, g, q, xbase);
            else        compute_tiles<4>(acc, A, bb, stg, t0, m, g, q, xbase);
        }
    }
}

extern "C" void kernel_launch(void* const* d_in, const int* in_sizes, int n_in,
                              void* d_out, int out_size) {
    const float* data1     = (const float*)d_in[0];
    const float* data2     = (const float*)d_in[1];
    const float* scale1    = (const float*)d_in[2];
    const float* scale2    = (const float*)d_in[3];
    /* d_in[4] = inter_scale, unused by the reference math */
    const float* out_scale = (const float*)d_in[5];

    reformat<<<512, 256>>>(data2);

    cudaFuncSetAttribute(corr_mma, cudaFuncAttributeMaxDynamicSharedMemorySize,
                         SMEM_BYTES);
    dim3 grid(32, 8);   // (y-pair, b)
    corr_mma<<<grid, NT, SMEM_BYTES>>>(data1, scale1, scale2, out_scale,
                                       (float*)d_out);
}